// round 6
// baseline (speedup 1.0000x reference)
#include <cuda_runtime.h>

#define N_NODES 100000
#define N_EDGES 3200000
#define EPS_F 1e-6f
#define EDGE_BLOCKS 1480
#define EDGE_THREADS 256

// Scratch (no allocations allowed).
__device__ float    g_v[N_NODES];        // packed node_features[:,0]
__device__ float    g_node_sum[N_NODES];
__device__ double   g_acc[5];            // p0, p1, p0^2, p1^2 sums
__device__ unsigned g_done;

__device__ __forceinline__ float warp_sum(float v) {
    #pragma unroll
    for (int o = 16; o; o >>= 1) v += __shfl_xor_sync(0xffffffffu, v, o);
    return v;
}

// Zero scratch + pack voltage column into a compact, cache-friendly table.
__global__ void init_kernel(const float* __restrict__ node_features) {
    int i = blockIdx.x * blockDim.x + threadIdx.x;
    if (i < N_NODES) {
        g_node_sum[i] = 0.0f;
        g_v[i] = node_features[i * 4];
    }
    if (i < 5) g_acc[i] = 0.0;
    if (i == 5) g_done = 0u;
}

// Single pass over edges (2 per thread, vectorized): scatter currents,
// accumulate variance moments. Last block then reduces node sums and
// writes the final scalar.
__global__ void __launch_bounds__(EDGE_THREADS) edge_kernel(
    const int*   __restrict__ edge_index,
    const float* __restrict__ edge_logits,
    const float* __restrict__ edge_params,
    float* __restrict__ out)
{
    const int tid    = blockIdx.x * blockDim.x + threadIdx.x;
    const int stride = gridDim.x * blockDim.x;
    const int2*   srcs = (const int2*)edge_index;
    const int2*   dsts = (const int2*)(edge_index + N_EDGES);
    const float2* lgs  = (const float2*)edge_logits;
    const float4* pars = (const float4*)edge_params;

    float s0 = 0.f, s1 = 0.f, q0 = 0.f, q1 = 0.f;

    for (int i = tid; i < N_EDGES / 2; i += stride) {
        int2   s  = __ldcs(&srcs[i]);
        int2   d  = __ldcs(&dsts[i]);
        float2 lg = __ldcs(&lgs[i]);
        float4 p  = __ldcs(&pars[i]);

        float prob0 = 1.0f / (1.0f + __expf(-lg.x));
        float prob1 = 1.0f / (1.0f + __expf(-lg.y));

        float cur0 = fabsf(g_v[s.x] - g_v[d.x]) / (p.x + p.y + EPS_F) * prob0;
        float cur1 = fabsf(g_v[s.y] - g_v[d.y]) / (p.z + p.w + EPS_F) * prob1;

        atomicAdd(&g_node_sum[d.x],  cur0);
        atomicAdd(&g_node_sum[s.x], -cur0);
        atomicAdd(&g_node_sum[d.y],  cur1);
        atomicAdd(&g_node_sum[s.y], -cur1);

        s0 += p.x + p.z;
        s1 += p.y + p.w;
        q0 += p.x * p.x + p.z * p.z;
        q1 += p.y * p.y + p.w * p.w;
    }

    // Block reduction of the moment accumulators -> double atomics.
    __shared__ float sm[4][8];
    int lane = threadIdx.x & 31;
    int wid  = threadIdx.x >> 5;

    s0 = warp_sum(s0); s1 = warp_sum(s1); q0 = warp_sum(q0); q1 = warp_sum(q1);
    if (lane == 0) { sm[0][wid] = s0; sm[1][wid] = s1; sm[2][wid] = q0; sm[3][wid] = q1; }
    __syncthreads();
    if (wid == 0) {
        float a = (lane < 8) ? sm[0][lane] : 0.f;
        float b = (lane < 8) ? sm[1][lane] : 0.f;
        float c = (lane < 8) ? sm[2][lane] : 0.f;
        float d = (lane < 8) ? sm[3][lane] : 0.f;
        a = warp_sum(a); b = warp_sum(b); c = warp_sum(c); d = warp_sum(d);
        if (lane == 0) {
            atomicAdd(&g_acc[0], (double)a);
            atomicAdd(&g_acc[1], (double)b);
            atomicAdd(&g_acc[2], (double)c);
            atomicAdd(&g_acc[3], (double)d);
        }
    }

    // Last-block: reduce node_sum^2 and finalize.
    __shared__ unsigned s_is_last;
    __threadfence();
    __syncthreads();
    if (threadIdx.x == 0)
        s_is_last = (atomicAdd(&g_done, 1u) == (unsigned)(gridDim.x - 1));
    __syncthreads();
    if (!s_is_last) return;

    float acc = 0.f;
    for (int i = threadIdx.x; i < N_NODES; i += blockDim.x) {
        float v = g_node_sum[i];
        acc += v * v;
    }
    __shared__ float smn[8];
    acc = warp_sum(acc);
    if (lane == 0) smn[wid] = acc;
    __syncthreads();
    if (wid == 0) {
        float a = (lane < 8) ? smn[lane] : 0.f;
        a = warp_sum(a);
        if (lane == 0) {
            double sum0 = g_acc[0], sum1 = g_acc[1];
            double sq0  = g_acc[2], sq1  = g_acc[3];
            const double E = (double)N_EDGES;
            double var0 = (sq0 - sum0 * sum0 / E) / (E - 1.0);
            double var1 = (sq1 - sum1 * sum1 / E) / (E - 1.0);
            double kvl = 0.5 * (var0 + var1);
            double kcl = (double)a / (double)N_NODES;
            out[0] = (float)(kcl + kvl);
        }
    }
}

extern "C" void kernel_launch(void* const* d_in, const int* in_sizes, int n_in,
                              void* d_out, int out_size)
{
    const float* node_features = (const float*)d_in[0];
    const int*   edge_index    = (const int*)d_in[1];
    const float* edge_logits   = (const float*)d_in[2];
    const float* edge_params   = (const float*)d_in[3];
    float* out = (float*)d_out;

    (void)in_sizes; (void)n_in; (void)out_size;

    init_kernel<<<(N_NODES + 255) / 256, 256>>>(node_features);
    edge_kernel<<<EDGE_BLOCKS, EDGE_THREADS>>>(edge_index, edge_logits, edge_params, out);
}

// round 7
// speedup vs baseline: 1.0170x; 1.0170x over previous
#include <cuda_runtime.h>

#define N_NODES 100000
#define N_EDGES 3200000
#define EPS_F 1e-6f
#define EDGE_BLOCKS 1480
#define EDGE_THREADS 256

// Scratch (no allocations allowed).
__device__ float    g_v[N_NODES];        // packed node_features[:,0]
__device__ float    g_node_sum[N_NODES];
__device__ double   g_acc[5];            // p0, p1, p0^2, p1^2 sums
__device__ unsigned g_done;

__device__ __forceinline__ float warp_sum(float v) {
    #pragma unroll
    for (int o = 16; o; o >>= 1) v += __shfl_xor_sync(0xffffffffu, v, o);
    return v;
}

// Zero scratch + pack voltage column into a compact, cache-friendly table.
__global__ void init_kernel(const float* __restrict__ node_features) {
    int i = blockIdx.x * blockDim.x + threadIdx.x;
    if (i < N_NODES) {
        g_node_sum[i] = 0.0f;
        g_v[i] = node_features[i * 4];
    }
    if (i < 5) g_acc[i] = 0.0;
    if (i == 5) g_done = 0u;
}

// One pass over edges (scalar, R5-style body): scatter currents, accumulate
// variance moments. Last block to finish reduces node sums and finalizes.
__global__ void __launch_bounds__(EDGE_THREADS) edge_kernel(
    const int*   __restrict__ edge_index,
    const float* __restrict__ edge_logits,
    const float2* __restrict__ edge_params,
    float* __restrict__ out)
{
    float s0 = 0.f, s1 = 0.f, q0 = 0.f, q1 = 0.f;

    const int stride = gridDim.x * blockDim.x;
    for (int e = blockIdx.x * blockDim.x + threadIdx.x; e < N_EDGES; e += stride) {
        int src = edge_index[e];
        int dst = edge_index[N_EDGES + e];
        float2 p  = edge_params[e];
        float  lg = edge_logits[e];

        float prob = 1.0f / (1.0f + __expf(-lg));

        float vdiff = fabsf(g_v[src] - g_v[dst]);
        float cur = vdiff / (p.x + p.y + EPS_F) * prob;

        atomicAdd(&g_node_sum[dst],  cur);
        atomicAdd(&g_node_sum[src], -cur);

        s0 += p.x;  s1 += p.y;
        q0 += p.x * p.x;  q1 += p.y * p.y;
    }

    // Block reduction of the moment accumulators -> double atomics.
    __shared__ float sm[4][8];
    int lane = threadIdx.x & 31;
    int wid  = threadIdx.x >> 5;

    s0 = warp_sum(s0); s1 = warp_sum(s1); q0 = warp_sum(q0); q1 = warp_sum(q1);
    if (lane == 0) { sm[0][wid] = s0; sm[1][wid] = s1; sm[2][wid] = q0; sm[3][wid] = q1; }
    __syncthreads();
    if (wid == 0) {
        float a = (lane < 8) ? sm[0][lane] : 0.f;
        float b = (lane < 8) ? sm[1][lane] : 0.f;
        float c = (lane < 8) ? sm[2][lane] : 0.f;
        float d = (lane < 8) ? sm[3][lane] : 0.f;
        a = warp_sum(a); b = warp_sum(b); c = warp_sum(c); d = warp_sum(d);
        if (lane == 0) {
            atomicAdd(&g_acc[0], (double)a);
            atomicAdd(&g_acc[1], (double)b);
            atomicAdd(&g_acc[2], (double)c);
            atomicAdd(&g_acc[3], (double)d);
        }
    }

    // Last-block: reduce node_sum^2 and finalize.
    __shared__ unsigned s_is_last;
    __threadfence();
    __syncthreads();
    if (threadIdx.x == 0)
        s_is_last = (atomicAdd(&g_done, 1u) == (unsigned)(gridDim.x - 1));
    __syncthreads();
    if (!s_is_last) return;

    float acc = 0.f;
    for (int i = threadIdx.x; i < N_NODES; i += blockDim.x) {
        float v = g_node_sum[i];
        acc += v * v;
    }
    __shared__ float smn[8];
    acc = warp_sum(acc);
    if (lane == 0) smn[wid] = acc;
    __syncthreads();
    if (wid == 0) {
        float a = (lane < 8) ? smn[lane] : 0.f;
        a = warp_sum(a);
        if (lane == 0) {
            double sum0 = g_acc[0], sum1 = g_acc[1];
            double sq0  = g_acc[2], sq1  = g_acc[3];
            const double E = (double)N_EDGES;
            double var0 = (sq0 - sum0 * sum0 / E) / (E - 1.0);
            double var1 = (sq1 - sum1 * sum1 / E) / (E - 1.0);
            double kvl = 0.5 * (var0 + var1);
            double kcl = (double)a / (double)N_NODES;
            out[0] = (float)(kcl + kvl);
        }
    }
}

extern "C" void kernel_launch(void* const* d_in, const int* in_sizes, int n_in,
                              void* d_out, int out_size)
{
    const float*  node_features = (const float*)d_in[0];
    const int*    edge_index    = (const int*)d_in[1];
    const float*  edge_logits   = (const float*)d_in[2];
    const float2* edge_params   = (const float2*)d_in[3];
    float* out = (float*)d_out;

    (void)in_sizes; (void)n_in; (void)out_size;

    init_kernel<<<(N_NODES + 255) / 256, 256>>>(node_features);
    edge_kernel<<<EDGE_BLOCKS, EDGE_THREADS>>>(edge_index, edge_logits, edge_params, out);
}